// round 3
// baseline (speedup 1.0000x reference)
#include <cuda_runtime.h>
#include <math.h>

#define N_ROWS      131072      // 512*256
#define DIMS        128
#define KCODES      1024
#define ROWS_PER_CTA 128
#define CHUNK       64
#define NCHUNK      (KCODES / CHUNK)
#define THREADS     256
#define Z_ELEMS     16777216    // N_ROWS * DIMS

// scratch (no allocations allowed)
__device__ float        g_cnorm[KCODES];
__device__ unsigned int g_hist[KCODES];
__device__ double       g_sqsum;

// ---------------------------------------------------------------------------
// prep: codebook norms + zero accumulators (re-run every launch: deterministic)
// ---------------------------------------------------------------------------
__global__ void vq_prep_kernel(const float* __restrict__ cb) {
    int id = blockIdx.x * blockDim.x + threadIdx.x;
    if (id < KCODES) {
        const float* row = cb + id * DIMS;
        float s = 0.f;
        #pragma unroll 4
        for (int d = 0; d < DIMS; d++) {
            float v = row[d];
            s = __fadd_rn(s, __fmul_rn(v, v));   // match "square then sum" (no fma)
        }
        g_cnorm[id] = s;
        g_hist[id] = 0u;
        if (id == 0) g_sqsum = 0.0;
    }
}

// ---------------------------------------------------------------------------
// main fused kernel: argmin + gather z + sq-err partial + histogram
// ---------------------------------------------------------------------------
extern __shared__ float smem[];

__global__ __launch_bounds__(THREADS, 2)
void vq_assign_kernel(const float* __restrict__ x,
                      const float* __restrict__ cb,
                      float* __restrict__ out) {
    float* x_s  = smem;                               // [128][128]
    float* c_s  = x_s + ROWS_PER_CTA * DIMS;          // transposed [128 d][64 codes]
    float* xn_s = c_s + DIMS * CHUNK;                 // [128]
    int*   idx_s = (int*)(xn_s + ROWS_PER_CTA);       // [128]

    const int t    = threadIdx.x;
    const int warp = t >> 5;
    const int lane = t & 31;
    const long long base = (long long)blockIdx.x * ROWS_PER_CTA;

    // ---- load x tile (coalesced float4) ----
    const float4* xg = (const float4*)x + base * (DIMS / 4);
    float4* x4 = (float4*)x_s;
    #pragma unroll
    for (int i = 0; i < 16; i++) x4[t + i * THREADS] = xg[t + i * THREADS];
    __syncthreads();

    // ---- per-row x_norm, replicating fl(sum(v*v)) left-to-right ----
    if (t < ROWS_PER_CTA) {
        const float* row = x_s + t * DIMS;
        float s = 0.f;
        #pragma unroll 8
        for (int d = 0; d < DIMS; d++) {
            float v = row[d];
            s = __fadd_rn(s, __fmul_rn(v, v));
        }
        xn_s[t] = s;
    }

    // running argmin: 16 rows x (val, idx) per thread
    float minv[16];
    int   mini[16];
    #pragma unroll
    for (int r = 0; r < 16; r++) { minv[r] = __int_as_float(0x7f800000); mini[r] = 0; }

    const float4* cg = (const float4*)cb;

    for (int chunk = 0; chunk < NCHUNK; chunk++) {
        __syncthreads();   // protect c_s from previous iteration's readers
        // ---- load 64-code chunk, transposed into c_s[d][code] ----
        #pragma unroll
        for (int i = 0; i < 8; i++) {
            int f  = t + i * THREADS;          // 0..2047
            int c  = f & 63;                   // code within chunk (lane-contiguous)
            int dg = f >> 6;                   // d-group
            float4 v = cg[(chunk * CHUNK + c) * (DIMS / 4) + dg];
            c_s[(dg * 4 + 0) * CHUNK + c] = v.x;
            c_s[(dg * 4 + 1) * CHUNK + c] = v.y;
            c_s[(dg * 4 + 2) * CHUNK + c] = v.z;
            c_s[(dg * 4 + 3) * CHUNK + c] = v.w;
        }
        __syncthreads();

        // ---- dots: 16 rows x 2 codes per thread over D=128 ----
        float acc0[16], acc1[16];
        #pragma unroll
        for (int r = 0; r < 16; r++) { acc0[r] = 0.f; acc1[r] = 0.f; }

        const float* xrow_base = x_s + warp * 16 * DIMS;
        #pragma unroll 2
        for (int dg = 0; dg < 32; dg++) {
            int d0 = dg * 4;
            float2 ca = *(const float2*)&c_s[(d0 + 0) * CHUNK + lane * 2];
            float2 cbv= *(const float2*)&c_s[(d0 + 1) * CHUNK + lane * 2];
            float2 cc = *(const float2*)&c_s[(d0 + 2) * CHUNK + lane * 2];
            float2 cd = *(const float2*)&c_s[(d0 + 3) * CHUNK + lane * 2];
            #pragma unroll
            for (int r = 0; r < 16; r++) {
                float4 xv = *(const float4*)&xrow_base[r * DIMS + d0];
                float a0 = acc0[r], a1 = acc1[r];
                a0 = fmaf(xv.x, ca.x,  a0);  a1 = fmaf(xv.x, ca.y,  a1);
                a0 = fmaf(xv.y, cbv.x, a0);  a1 = fmaf(xv.y, cbv.y, a1);
                a0 = fmaf(xv.z, cc.x,  a0);  a1 = fmaf(xv.z, cc.y,  a1);
                a0 = fmaf(xv.w, cd.x,  a0);  a1 = fmaf(xv.w, cd.y,  a1);
                acc0[r] = a0; acc1[r] = a1;
            }
        }

        // ---- scores: dist = fl((x_norm + c_norm) - 2*dot), clamp at 0 ----
        int kb = chunk * CHUNK + lane * 2;
        float cn0 = g_cnorm[kb];
        float cn1 = g_cnorm[kb + 1];
        #pragma unroll
        for (int r = 0; r < 16; r++) {
            float xn = xn_s[warp * 16 + r];
            // 2*dot is exact (x2), so fmaf == (t - 2*dot) with one rounding: matches ref
            float s0 = fmaxf(fmaf(-2.0f, acc0[r], __fadd_rn(xn, cn0)), 0.0f);
            float s1 = fmaxf(fmaf(-2.0f, acc1[r], __fadd_rn(xn, cn1)), 0.0f);
            if (s0 < minv[r]) { minv[r] = s0; mini[r] = kb; }
            if (s1 < minv[r]) { minv[r] = s1; mini[r] = kb + 1; }
        }
    }

    // ---- warp-level argmin reduce (lower index wins ties, like jnp.argmin) ----
    #pragma unroll
    for (int r = 0; r < 16; r++) {
        float v = minv[r]; int idx = mini[r];
        #pragma unroll
        for (int off = 16; off >= 1; off >>= 1) {
            float ov = __shfl_down_sync(0xffffffffu, v, off);
            int   oi = __shfl_down_sync(0xffffffffu, idx, off);
            if (ov < v || (ov == v && oi < idx)) { v = ov; idx = oi; }
        }
        if (lane == 0) idx_s[warp * 16 + r] = idx;
    }
    __syncthreads();

    // ---- epilogue: gather z, write out, accumulate (z-x)^2, histogram ----
    float lsum = 0.f;
    float4* out4 = (float4*)out;
    #pragma unroll
    for (int i = 0; i < 16; i++) {
        int f = t + i * THREADS;             // 0..4095
        int row = f >> 5, d4 = f & 31;
        int k = idx_s[row];
        float4 zv = cg[k * (DIMS / 4) + d4]; // codebook is L2-hot
        float4 xv = x4[row * (DIMS / 4) + d4];
        out4[(base + row) * (DIMS / 4) + d4] = zv;
        float e0 = zv.x - xv.x, e1 = zv.y - xv.y;
        float e2 = zv.z - xv.z, e3 = zv.w - xv.w;
        lsum += e0 * e0 + e1 * e1 + e2 * e2 + e3 * e3;
    }
    #pragma unroll
    for (int off = 16; off >= 1; off >>= 1)
        lsum += __shfl_down_sync(0xffffffffu, lsum, off);
    if (lane == 0) xn_s[warp] = lsum;        // xn_s reusable after last sync
    __syncthreads();
    if (t == 0) {
        float bsum = 0.f;
        #pragma unroll
        for (int w = 0; w < 8; w++) bsum += xn_s[w];
        atomicAdd(&g_sqsum, (double)bsum);
    }
    if (t < ROWS_PER_CTA) atomicAdd(&g_hist[idx_s[t]], 1u);
}

// ---------------------------------------------------------------------------
// finalize: losses + perplexity
// ---------------------------------------------------------------------------
__global__ void vq_finalize_kernel(float* __restrict__ out) {
    __shared__ float partial[32];
    int t = threadIdx.x;  // 1024 threads, one per code
    float p = (float)g_hist[t] / (float)N_ROWS;
    float term = __fmul_rn(p, logf(__fadd_rn(p, 1e-10f)));
    #pragma unroll
    for (int off = 16; off >= 1; off >>= 1)
        term += __shfl_down_sync(0xffffffffu, term, off);
    if ((t & 31) == 0) partial[t >> 5] = term;
    __syncthreads();
    if (t < 32) {
        float v = partial[t];
        #pragma unroll
        for (int off = 16; off >= 1; off >>= 1)
            v += __shfl_down_sync(0xffffffffu, v, off);
        if (t == 0) {
            float loss = (float)(g_sqsum / (double)Z_ELEMS);
            out[Z_ELEMS + 0] = loss;        // quantization_loss
            out[Z_ELEMS + 1] = loss;        // commitment_loss (numerically equal)
            out[Z_ELEMS + 2] = expf(-v);    // perplexity
        }
    }
}

// ---------------------------------------------------------------------------
extern "C" void kernel_launch(void* const* d_in, const int* in_sizes, int n_in,
                              void* d_out, int out_size) {
    const float* x  = (const float*)d_in[0];   // [512,256,128] fp32
    const float* cb = (const float*)d_in[1];   // [1024,128] fp32
    float* out = (float*)d_out;

    const size_t smem_bytes =
        (ROWS_PER_CTA * DIMS + DIMS * CHUNK + ROWS_PER_CTA) * sizeof(float)
        + ROWS_PER_CTA * sizeof(int);          // 99,328 B

    cudaFuncSetAttribute(vq_assign_kernel,
                         cudaFuncAttributeMaxDynamicSharedMemorySize,
                         (int)smem_bytes);

    vq_prep_kernel<<<4, 256>>>(cb);
    vq_assign_kernel<<<N_ROWS / ROWS_PER_CTA, THREADS, smem_bytes>>>(x, cb, out);
    vq_finalize_kernel<<<1, 1024>>>(out);
}

// round 5
// speedup vs baseline: 1.0229x; 1.0229x over previous
#include <cuda_runtime.h>
#include <math.h>

#define N_ROWS    131072         // 512*256
#define DIMS      128
#define KCODES    1024
#define ROWS_CTA  64
#define CHUNK     128            // codes per chunk
#define NCHUNK    (KCODES / CHUNK)   // 8
#define THREADS   256
#define Z_ELEMS   16777216
#define NTILES    (N_ROWS / ROWS_CTA)  // 2048

// scratch (no allocations allowed)
__device__ float        g_cnorm[KCODES];
__device__ unsigned int g_hist[KCODES];
__device__ double       g_sqsum;

// ---- f32x2 packed-FMA helpers (sm_10x) --------------------------------------
#define FMA2(acc, a, b) \
    asm("fma.rn.f32x2 %0, %1, %2, %0;" : "+l"(acc) : "l"(a), "l"(b))
#define PACK_DUP(dst, s) \
    asm("mov.b64 %0, {%1, %1};" : "=l"(dst) : "r"(s))
#define UNPACK2(lo, hi, p) \
    asm("mov.b64 {%0, %1}, %2;" : "=r"(lo), "=r"(hi) : "l"(p))
#define LDS_V2B64(p0, p1, addr) \
    asm("ld.shared.v2.b64 {%0, %1}, [%2];" : "=l"(p0), "=l"(p1) : "r"(addr))

// ---------------------------------------------------------------------------
// prep: codebook norms (exact sequential order) + zero accumulators
// ---------------------------------------------------------------------------
__global__ void vq_prep_kernel(const float* __restrict__ cb) {
    int id = blockIdx.x * blockDim.x + threadIdx.x;
    if (id < KCODES) {
        const float4* r4 = (const float4*)(cb + id * DIMS);
        float s = 0.f;
        #pragma unroll
        for (int i = 0; i < 32; i++) {        // full unroll -> high MLP
            float4 v = r4[i];
            s = __fadd_rn(s, __fmul_rn(v.x, v.x));
            s = __fadd_rn(s, __fmul_rn(v.y, v.y));
            s = __fadd_rn(s, __fmul_rn(v.z, v.z));
            s = __fadd_rn(s, __fmul_rn(v.w, v.w));
        }
        g_cnorm[id] = s;
        g_hist[id] = 0u;
        if (id == 0) g_sqsum = 0.0;
    }
}

// ---------------------------------------------------------------------------
// main fused kernel: FFMA2 dots + argmin + gather z + sq-err + histogram
// smem: x_t (transposed/swizzled) | c_s (transposed) | cn_s | xn_s | idx_s | red
// ---------------------------------------------------------------------------
extern __shared__ float smem[];

__global__ __launch_bounds__(THREADS, 2)
void vq_assign_kernel(const float* __restrict__ x,
                      const float* __restrict__ cb,
                      float* __restrict__ out) {
    float* x_t  = smem;                         // [128 d][64 rows] swizzled (32KB)
    float* c_s  = x_t + DIMS * ROWS_CTA;        // [128 d][128 codes]       (64KB)
    float* cn_s = c_s + DIMS * CHUNK;           // [1024]
    float* xn_s = cn_s + KCODES;                // [64]
    int*   idx_s = (int*)(xn_s + ROWS_CTA);     // [64]
    float* red_s = (float*)(idx_s + ROWS_CTA);  // [8]

    const int t    = threadIdx.x;
    const int warp = t >> 5;
    const int lane = t & 31;
    const int tile = blockIdx.x;

    const unsigned xt_b = (unsigned)__cvta_generic_to_shared(x_t);

    // ---- load x tile: coalesced float4, store transposed + swizzled ----
    // swizzle: slot = row ^ (4*((d>>2)&7)); keeps 4-row groups aligned/contiguous
    const float4* xg = (const float4*)x + (size_t)tile * (ROWS_CTA * DIMS / 4);
    #pragma unroll
    for (int i = 0; i < 8; i++) {
        int f = t + i * THREADS;                // 0..2047
        int row = f >> 5, d4 = f & 31;
        float4 v = xg[f];
        int s = 4 * (d4 & 7);
        int slot = row ^ s;
        float* p = x_t + (4 * d4) * ROWS_CTA + slot;
        p[0 * ROWS_CTA] = v.x;
        p[1 * ROWS_CTA] = v.y;
        p[2 * ROWS_CTA] = v.z;
        p[3 * ROWS_CTA] = v.w;
    }
    // codebook norms to smem
    #pragma unroll
    for (int j = t; j < KCODES; j += THREADS) cn_s[j] = g_cnorm[j];
    __syncthreads();

    // ---- per-row x_norm, exact sequential fl(sum(v*v)) order d=0..127 ----
    if (t < ROWS_CTA) {
        float s = 0.f;
        #pragma unroll 16
        for (int d = 0; d < DIMS; d++) {
            float v = x_t[d * ROWS_CTA + (t ^ (4 * ((d >> 2) & 7)))];
            s = __fadd_rn(s, __fmul_rn(v, v));
        }
        xn_s[t] = s;
    }
    __syncthreads();

    // warp's 8 rows -> x_norm in registers
    float xn[8];
    #pragma unroll
    for (int r = 0; r < 8; r++) xn[r] = xn_s[warp * 8 + r];

    // running argmin per row
    float minv[8]; int mini[8];
    #pragma unroll
    for (int r = 0; r < 8; r++) { minv[r] = __int_as_float(0x7f800000); mini[r] = 0; }

    const float4* cg4 = (const float4*)cb;
    const int w8 = warp * 8;

    for (int chunk = 0; chunk < NCHUNK; chunk++) {
        __syncthreads();   // prior chunk's readers done with c_s
        // ---- fill c_s transposed [d][128 codes]; conflict-free STS ----
        #pragma unroll
        for (int i = 0; i < 16; i++) {
            int f = t + i * THREADS;            // 0..4095
            int k = f & 127, dg = f >> 7;       // dg 0..31
            float4 v = cg4[(chunk * CHUNK + k) * 32 + dg];
            float* p = c_s + (4 * dg) * CHUNK + k;
            p[0 * CHUNK] = v.x;
            p[1 * CHUNK] = v.y;
            p[2 * CHUNK] = v.z;
            p[3 * CHUNK] = v.w;
        }
        __syncthreads();

        // ---- accumulate: 4 row-pairs x 4 codes, packed f32x2 ----
        unsigned long long acc[4][4];
        #pragma unroll
        for (int p = 0; p < 4; p++)
            #pragma unroll
            for (int c = 0; c < 4; c++) acc[p][c] = 0ull;

        #pragma unroll 2
        for (int dg = 0; dg < 32; dg++) {
            int s  = 4 * (dg & 7);
            unsigned a0 = xt_b + (unsigned)(((dg * 4) * ROWS_CTA + ((w8 + 0) ^ s)) * 4);
            unsigned a1 = xt_b + (unsigned)(((dg * 4) * ROWS_CTA + ((w8 + 4) ^ s)) * 4);
            #pragma unroll
            for (int j = 0; j < 4; j++) {       // d = 4*dg + j
                int d = 4 * dg + j;
                // codes: lane*4 .. lane*4+3 (contiguous float4)
                float4 cv = *(const float4*)&c_s[d * CHUNK + lane * 4];
                unsigned long long cc0, cc1, cc2, cc3;
                PACK_DUP(cc0, __float_as_uint(cv.x));
                PACK_DUP(cc1, __float_as_uint(cv.y));
                PACK_DUP(cc2, __float_as_uint(cv.z));
                PACK_DUP(cc3, __float_as_uint(cv.w));
                // x row-pairs (broadcast 16B loads): rows w8..w8+3, w8+4..w8+7
                unsigned long long xp0, xp1, xp2, xp3;
                LDS_V2B64(xp0, xp1, a0 + (unsigned)(j * ROWS_CTA * 4));
                LDS_V2B64(xp2, xp3, a1 + (unsigned)(j * ROWS_CTA * 4));
                FMA2(acc[0][0], xp0, cc0); FMA2(acc[0][1], xp0, cc1);
                FMA2(acc[0][2], xp0, cc2); FMA2(acc[0][3], xp0, cc3);
                FMA2(acc[1][0], xp1, cc0); FMA2(acc[1][1], xp1, cc1);
                FMA2(acc[1][2], xp1, cc2); FMA2(acc[1][3], xp1, cc3);
                FMA2(acc[2][0], xp2, cc0); FMA2(acc[2][1], xp2, cc1);
                FMA2(acc[2][2], xp2, cc2); FMA2(acc[2][3], xp2, cc3);
                FMA2(acc[3][0], xp3, cc0); FMA2(acc[3][1], xp3, cc1);
                FMA2(acc[3][2], xp3, cc2); FMA2(acc[3][3], xp3, cc3);
            }
        }

        // ---- scores: dist = max(fl((xn+cn) - 2*dot), 0), exact round-1 form ----
        int kb = chunk * CHUNK + lane * 4;
        float cn0 = cn_s[kb], cn1 = cn_s[kb + 1], cn2 = cn_s[kb + 2], cn3 = cn_s[kb + 3];
        #pragma unroll
        for (int p = 0; p < 4; p++) {
            int r0 = 2 * p, r1 = 2 * p + 1;
            #pragma unroll
            for (int c = 0; c < 4; c++) {
                unsigned lo, hi;
                UNPACK2(lo, hi, acc[p][c]);
                float cn = (c == 0) ? cn0 : (c == 1) ? cn1 : (c == 2) ? cn2 : cn3;
                float d0 = fmaxf(fmaf(-2.0f, __uint_as_float(lo), __fadd_rn(xn[r0], cn)), 0.0f);
                float d1 = fmaxf(fmaf(-2.0f, __uint_as_float(hi), __fadd_rn(xn[r1], cn)), 0.0f);
                if (d0 < minv[r0]) { minv[r0] = d0; mini[r0] = kb + c; }
                if (d1 < minv[r1]) { minv[r1] = d1; mini[r1] = kb + c; }
            }
        }
    }

    // ---- warp argmin per row (lower index wins ties) ----
    #pragma unroll
    for (int r = 0; r < 8; r++) {
        float v = minv[r]; int idx = mini[r];
        #pragma unroll
        for (int off = 16; off >= 1; off >>= 1) {
            float ov = __shfl_down_sync(0xffffffffu, v, off);
            int   oi = __shfl_down_sync(0xffffffffu, idx, off);
            if (ov < v || (ov == v && oi < idx)) { v = ov; idx = oi; }
        }
        if (lane == 0) idx_s[w8 + r] = idx;
    }
    __syncthreads();

    // ---- epilogue: gather z, write out, (z-x)^2 partial, histogram ----
    float lsum = 0.f;
    float4* out4 = (float4*)out;
    #pragma unroll
    for (int i = 0; i < 8; i++) {
        int f = t + i * THREADS;                // 0..2047
        int row = f >> 5, d4 = f & 31;
        int k = idx_s[row];
        float4 zv = cg4[k * 32 + d4];
        int s = 4 * (d4 & 7);
        int slot = row ^ s;
        const float* p = x_t + (4 * d4) * ROWS_CTA + slot;
        float x0 = p[0 * ROWS_CTA], x1 = p[1 * ROWS_CTA];
        float x2 = p[2 * ROWS_CTA], x3 = p[3 * ROWS_CTA];
        out4[(size_t)(tile * ROWS_CTA + row) * 32 + d4] = zv;
        float e0 = zv.x - x0, e1 = zv.y - x1, e2 = zv.z - x2, e3 = zv.w - x3;
        lsum += e0 * e0 + e1 * e1 + e2 * e2 + e3 * e3;
    }
    #pragma unroll
    for (int off = 16; off >= 1; off >>= 1)
        lsum += __shfl_down_sync(0xffffffffu, lsum, off);
    if (lane == 0) red_s[warp] = lsum;
    __syncthreads();
    if (t == 0) {
        float bsum = 0.f;
        #pragma unroll
        for (int w = 0; w < 8; w++) bsum += red_s[w];
        atomicAdd(&g_sqsum, (double)bsum);
    }
    if (t < ROWS_CTA) atomicAdd(&g_hist[idx_s[t]], 1u);
}

// ---------------------------------------------------------------------------
// finalize: losses + perplexity
// ---------------------------------------------------------------------------
__global__ void vq_finalize_kernel(float* __restrict__ out) {
    __shared__ float partial[32];
    int t = threadIdx.x;  // 1024 threads, one per code
    float p = (float)g_hist[t] / (float)N_ROWS;
    float term = __fmul_rn(p, logf(__fadd_rn(p, 1e-10f)));
    #pragma unroll
    for (int off = 16; off >= 1; off >>= 1)
        term += __shfl_down_sync(0xffffffffu, term, off);
    if ((t & 31) == 0) partial[t >> 5] = term;
    __syncthreads();
    if (t < 32) {
        float v = partial[t];
        #pragma unroll
        for (int off = 16; off >= 1; off >>= 1)
            v += __shfl_down_sync(0xffffffffu, v, off);
        if (t == 0) {
            float loss = (float)(g_sqsum / (double)Z_ELEMS);
            out[Z_ELEMS + 0] = loss;        // quantization_loss
            out[Z_ELEMS + 1] = loss;        // commitment_loss (numerically equal)
            out[Z_ELEMS + 2] = expf(-v);    // perplexity
        }
    }
}

// ---------------------------------------------------------------------------
extern "C" void kernel_launch(void* const* d_in, const int* in_sizes, int n_in,
                              void* d_out, int out_size) {
    const float* x  = (const float*)d_in[0];   // [512,256,128] fp32
    const float* cb = (const float*)d_in[1];   // [1024,128] fp32
    float* out = (float*)d_out;

    const size_t smem_bytes =
        (DIMS * ROWS_CTA            // x_t
       + DIMS * CHUNK               // c_s
       + KCODES                     // cn_s
       + ROWS_CTA) * sizeof(float)  // xn_s
       + ROWS_CTA * sizeof(int)     // idx_s
       + 8 * sizeof(float);         // red_s   => ~103 KB

    cudaFuncSetAttribute(vq_assign_kernel,
                         cudaFuncAttributeMaxDynamicSharedMemorySize,
                         (int)smem_bytes);

    vq_prep_kernel<<<8, 128>>>(cb);
    vq_assign_kernel<<<NTILES, THREADS, smem_bytes>>>(x, cb, out);
    vq_finalize_kernel<<<1, 1024>>>(out);
}